// round 6
// baseline (speedup 1.0000x reference)
#include <cuda_runtime.h>
#include <cstdint>

#define B_   8
#define N_   4096
#define S_   1024
#define NS_  32
#define CIN  64
#define CMLP 128
#define COUT 256
#define R2_  0.0225f   // 0.15^2

// ---------------- scratch ----------------
__device__ float  g_W[CIN * COUT];
__device__ float  g_bias2[COUT];
__device__ float  g_feats2[(size_t)B_ * N_ * COUT];
__device__ int    g_fps[B_ * S_];
__device__ int    g_gidx[B_ * S_ * NS_];
__device__ int    g_cnt[B_ * N_];
__device__ float  g_sum[COUT];
__device__ float  g_sumsq[COUT];
__device__ float4 g_xyz4[B_ * N_];     // xyz staged as float4 (orig order)
__device__ float4 g_pts4[B_ * N_];     // cell-permuted points (x,y,z,orig-id)

// ---------------- L1: prep ----------------
__global__ __launch_bounds__(256) void prep_kernel(const float* __restrict__ xyz,
                                                   const float* __restrict__ W1,
                                                   const float* __restrict__ b1,
                                                   const float* __restrict__ Wc,
                                                   const float* __restrict__ bc) {
    int bx = blockIdx.x, tid = threadIdx.x;
    if (bx < 64) {
        float acc = 0.f;
        const float* w1 = W1 + bx * CMLP;
#pragma unroll 8
        for (int m = 0; m < CMLP; m++) acc = fmaf(w1[m], Wc[m * COUT + tid], acc);
        g_W[bx * COUT + tid] = acc;
    } else if (bx == 64) {
        float acc = bc[tid];
#pragma unroll 8
        for (int m = 0; m < CMLP; m++) acc = fmaf(b1[m], Wc[m * COUT + tid], acc);
        g_bias2[tid] = acc;
        g_sum[tid] = 0.f;
        g_sumsq[tid] = 0.f;
    } else if (bx < 81) {
        int base = (bx - 65) * 2048 + tid;
#pragma unroll
        for (int i = 0; i < 8; i++) g_cnt[base + i * 256] = 0;
    } else {
        int base = (bx - 81) * 1024 + tid;
#pragma unroll
        for (int i = 0; i < 4; i++) {
            int p = base + i * 256;
            g_xyz4[p] = make_float4(xyz[p * 3 + 0], xyz[p * 3 + 1], xyz[p * 3 + 2], 0.f);
        }
    }
}

// ---------------- L2: fused FPS (blocks 0..7, 512 thr) + feats2 GEMM ----------------
__global__ __launch_bounds__(512) void fps_gemm_kernel(const float* __restrict__ xyz,
                                                       const float* __restrict__ points) {
    __shared__ __align__(16) char smem_raw[64 * 68 * 4];   // 17.4 KB union
    const int tid = threadIdx.x;

    if (blockIdx.x < B_) {
        // ============ FPS: one CTA (512 thr), 16^3 Morton sort, warp pruning ============
        const int b = blockIdx.x;
        const float* X = xyz + (size_t)b * N_ * 3;
        const int lane = tid & 31, w = tid >> 5;        // 16 warps
        const int base = tid * 8;                       // 8 pts/thread
        const size_t bN = (size_t)b * N_;

        unsigned* cells = (unsigned*)smem_raw;                   // [4096] 16 KB
        unsigned* wsum  = (unsigned*)(smem_raw + 16384);         // [16]
        uint2*    swp   = (uint2*)(smem_raw + 16384 + 64);       // [2][16]

        // ---- prologue: counting-sort into 16x16x16 Morton cells ----
#pragma unroll
        for (int i = 0; i < 8; i++) cells[tid + i * 512] = 0;
        __syncthreads();

        float lx[8], ly[8], lz[8];
        int cid[8];
#pragma unroll
        for (int i = 0; i < 8; i++) {
            int p = base + i;
            lx[i] = X[p * 3 + 0]; ly[i] = X[p * 3 + 1]; lz[i] = X[p * 3 + 2];
            int ix = min(15, (int)(lx[i] * 16.f));
            int iy = min(15, (int)(ly[i] * 16.f));
            int iz = min(15, (int)(lz[i] * 16.f));
            int m = (ix & 1) | ((iy & 1) << 1) | ((iz & 1) << 2)
                  | ((ix & 2) << 2) | ((iy & 2) << 3) | ((iz & 2) << 4)
                  | ((ix & 4) << 4) | ((iy & 4) << 5) | ((iz & 4) << 6)
                  | ((ix & 8) << 6) | ((iy & 8) << 7) | ((iz & 8) << 8);
            cid[i] = m;
            atomicAdd(&cells[m], 1u);
        }
        __syncthreads();

        // exclusive scan over 4096 cells (8 consecutive per thread)
        {
            unsigned c8[8], tsum = 0;
#pragma unroll
            for (int i = 0; i < 8; i++) { c8[i] = cells[tid * 8 + i]; tsum += c8[i]; }
            unsigned inc = tsum;
#pragma unroll
            for (int o = 1; o < 32; o <<= 1) {
                unsigned n = __shfl_up_sync(0xffffffffu, inc, o);
                if (lane >= o) inc += n;
            }
            if (lane == 31) wsum[w] = inc;
            __syncthreads();
            if (tid < 16) {
                unsigned t = wsum[tid], s = t;
#pragma unroll
                for (int o = 1; o < 16; o <<= 1) {
                    unsigned n = __shfl_up_sync(0xffffu, s, o);
                    if (tid >= o) s += n;
                }
                wsum[tid] = s - t;
            }
            __syncthreads();
            unsigned run = wsum[w] + inc - tsum;
#pragma unroll
            for (int i = 0; i < 8; i++) { cells[tid * 8 + i] = run; run += c8[i]; }
            __syncthreads();
        }

        // scatter with original ids
#pragma unroll
        for (int i = 0; i < 8; i++) {
            unsigned pos = atomicAdd(&cells[cid[i]], 1u);
            g_pts4[bN + pos] = make_float4(lx[i], ly[i], lz[i], __int_as_float(base + i));
        }
        __syncthreads();

        // reload own 8 permuted points; warp bbox (all coords in [0,1])
        float px[8], py[8], pz[8], dm[8];
        int   pid[8];
        float tlx = 1e30f, tly = 1e30f, tlz = 1e30f;
        float thx = -1e30f, thy = -1e30f, thz = -1e30f;
#pragma unroll
        for (int i = 0; i < 8; i++) {
            float4 v = g_pts4[bN + base + i];
            px[i] = v.x; py[i] = v.y; pz[i] = v.z;
            pid[i] = __float_as_int(v.w);
            dm[i] = 1e10f;
            tlx = fminf(tlx, v.x); thx = fmaxf(thx, v.x);
            tly = fminf(tly, v.y); thy = fmaxf(thy, v.y);
            tlz = fminf(tlz, v.z); thz = fmaxf(thz, v.z);
        }
        const float wlx = __uint_as_float(__reduce_min_sync(0xffffffffu, __float_as_uint(tlx)));
        const float wly = __uint_as_float(__reduce_min_sync(0xffffffffu, __float_as_uint(tly)));
        const float wlz = __uint_as_float(__reduce_min_sync(0xffffffffu, __float_as_uint(tlz)));
        const float whx = __uint_as_float(__reduce_max_sync(0xffffffffu, __float_as_uint(thx)));
        const float why = __uint_as_float(__reduce_max_sync(0xffffffffu, __float_as_uint(thy)));
        const float whz = __uint_as_float(__reduce_max_sync(0xffffffffu, __float_as_uint(thz)));

        if (tid == 0) g_fps[b * S_ + 0] = 0;
        float4 c4 = __ldg(&g_xyz4[bN + 0]);
        float cx = c4.x, cy = c4.y, cz = c4.z;
        unsigned tmaxu  = __float_as_uint(1e10f);   // per-lane max(dm)
        unsigned wTmaxu = __float_as_uint(1e10f);   // cached warp max (uniform)
        unsigned wWinu  = 0u;                        // cached warp winner (~pid)

        for (int it = 1; it < S_; ++it) {
            // conservative lower bound centroid -> warp bbox
            float tx = fmaxf(fmaxf(wlx - cx, cx - whx), 0.f);
            float ty = fmaxf(fmaxf(wly - cy, cy - why), 0.f);
            float tz = fmaxf(fmaxf(wlz - cz, cz - whz), 0.f);
            float wLB = tx * tx;
            wLB = fmaf(ty, ty, wLB);
            wLB = fmaf(tz, tz, wLB);

            if (wLB * 0.999999f < __uint_as_float(wTmaxu)) {   // whole-warp scan
                float bestv = -1.f;
#pragma unroll
                for (int i = 0; i < 8; i++) {
                    float dx = px[i] - cx, dy = py[i] - cy, dz = pz[i] - cz;
                    float d = fmaf(dz, dz, fmaf(dy, dy, dx * dx));
                    float v = fminf(dm[i], d);
                    dm[i] = v;
                    bestv = fmaxf(bestv, v);
                }
                unsigned ub = __float_as_uint(bestv);
                unsigned m1 = __reduce_max_sync(0xffffffffu, ub);
                unsigned cand = 0u;
                if (ub == m1) {
                    float fM = __uint_as_float(m1);
                    int mid = 0x7fffffff;
#pragma unroll
                    for (int i = 0; i < 8; i++)
                        if (dm[i] == fM) mid = min(mid, pid[i]);
                    cand = ~(unsigned)mid;
                }
                wWinu = __reduce_max_sync(0xffffffffu, cand);
                tmaxu = ub;
                wTmaxu = m1;
            }
            // else: exact skip — cached (wTmaxu, wWinu, tmaxu) remain valid

            const int pr = it & 1;
            if (lane == 0) swp[pr * 16 + w] = make_uint2(wTmaxu, wWinu);
            __syncthreads();                                   // the ONLY barrier

            uint2 pv = swp[pr * 16 + (lane & 15)];
            unsigned M2 = __reduce_max_sync(0xffffffffu, pv.x);
            unsigned c2 = (pv.x == M2) ? pv.y : 0u;
            unsigned I2 = __reduce_max_sync(0xffffffffu, c2);
            int far = (int)(~I2);

            if (tid == 0) g_fps[b * S_ + it] = far;
            float4 cc = __ldg(&g_xyz4[bN + far]);
            cx = cc.x; cy = cc.y; cz = cc.z;
        }
    } else {
        // ============ GEMM (512 thr): feats2 = points @ W + bias2 ============
        float (*As)[68] = (float (*)[68])smem_raw;
        const int gb = blockIdx.x - B_;
        const int rt = gb & 511;
        const int ct = gb >> 9;

#pragma unroll
        for (int i = 0; i < 2; i++) {
            int f = tid + i * 512;
            int r = f >> 4, k4 = f & 15;
            float4 v = *(const float4*)(points + ((size_t)(rt * 64 + r)) * 64 + k4 * 4);
            As[k4 * 4 + 0][r] = v.x;
            As[k4 * 4 + 1][r] = v.y;
            As[k4 * 4 + 2][r] = v.z;
            As[k4 * 4 + 3][r] = v.w;
        }
        __syncthreads();

        const int col0 = ct * 128 + (tid & 31) * 4;
        const int r0   = (tid >> 5) * 4;

        float acc[4][4];
#pragma unroll
        for (int i = 0; i < 4; i++)
#pragma unroll
            for (int j = 0; j < 4; j++) acc[i][j] = 0.f;

#pragma unroll 8
        for (int k = 0; k < 64; k++) {
            float4 b4 = *(const float4*)(g_W + k * COUT + col0);
            float4 a4 = *(const float4*)&As[k][r0];
            float a[4] = {a4.x, a4.y, a4.z, a4.w};
            float bv[4] = {b4.x, b4.y, b4.z, b4.w};
#pragma unroll
            for (int i = 0; i < 4; i++)
#pragma unroll
                for (int j = 0; j < 4; j++)
                    acc[i][j] = fmaf(a[i], bv[j], acc[i][j]);
        }

        float4 bb = *(const float4*)(g_bias2 + col0);
#pragma unroll
        for (int i = 0; i < 4; i++) {
            float4 o;
            o.x = acc[i][0] + bb.x;
            o.y = acc[i][1] + bb.y;
            o.z = acc[i][2] + bb.z;
            o.w = acc[i][3] + bb.w;
            *(float4*)(g_feats2 + ((size_t)(rt * 64 + r0 + i)) * COUT + col0) = o;
        }
    }
}

// ---------------- L3: ball query (one warp per query, float4 xyz) ----------------
__global__ __launch_bounds__(256) void ball_kernel() {
    const int w = threadIdx.x >> 5, lane = threadIdx.x & 31;
    const int q = blockIdx.x * 8 + w;
    const int b = q >> 10;
    const float4* X4 = g_xyz4 + (size_t)b * N_;
    const int ci = g_fps[q];
    float4 c = __ldg(&X4[ci]);

    int cnt = 0, first = -1;
    int* out = g_gidx + q * NS_;

    for (int base = 0; base < N_; base += 32) {
        int p = base + lane;
        float4 v = __ldg(&X4[p]);
        float dx = v.x - c.x, dy = v.y - c.y, dz = v.z - c.z;
        float d = fmaf(dz, dz, fmaf(dy, dy, dx * dx));
        bool in = (d <= R2_);
        unsigned bal = __ballot_sync(0xffffffffu, in);
        if (first < 0 && bal) first = base + __ffs(bal) - 1;
        int slot = cnt + __popc(bal & ((1u << lane) - 1));
        if (in && slot < NS_) {
            out[slot] = p;
            atomicAdd(&g_cnt[b * N_ + p], 1);
        }
        cnt += __popc(bal);
        if (cnt >= NS_) break;
    }
    if (cnt < NS_) {
        for (int s2 = cnt + lane; s2 < NS_; s2 += 32) out[s2] = first;
        if (lane == 0) atomicAdd(&g_cnt[b * N_ + first], NS_ - cnt);
    }
}

// ---------------- L4: count-weighted BN stats (1024 blocks, 32 rows each) ----------------
__global__ __launch_bounds__(256) void stats_kernel() {
    __shared__ float cf[32];
    __shared__ float4 red[64][4][2];
    const int tid = threadIdx.x;
    const int row0 = blockIdx.x * 32;
    if (tid < 32) cf[tid] = (float)g_cnt[row0 + tid];
    __syncthreads();

    const int cq = tid & 63;         // channel quad 0..63
    const int sr = tid >> 6;         // subrow group 0..3 (8 rows each)
    float4 s  = make_float4(0.f, 0.f, 0.f, 0.f);
    float4 s2 = make_float4(0.f, 0.f, 0.f, 0.f);
#pragma unroll
    for (int k = 0; k < 8; k++) {
        int r = sr * 8 + k;
        float c = cf[r];
        float4 v = *(const float4*)(g_feats2 + (size_t)(row0 + r) * COUT + cq * 4);
        float ax = c * v.x, ay = c * v.y, az = c * v.z, aw = c * v.w;
        s.x += ax; s.y += ay; s.z += az; s.w += aw;
        s2.x = fmaf(ax, v.x, s2.x);
        s2.y = fmaf(ay, v.y, s2.y);
        s2.z = fmaf(az, v.z, s2.z);
        s2.w = fmaf(aw, v.w, s2.w);
    }
    red[cq][sr][0] = s;
    red[cq][sr][1] = s2;
    __syncthreads();

    if (sr == 0) {
#pragma unroll
        for (int j = 1; j < 4; j++) {
            float4 a = red[cq][j][0], b2 = red[cq][j][1];
            s.x += a.x; s.y += a.y; s.z += a.z; s.w += a.w;
            s2.x += b2.x; s2.y += b2.y; s2.z += b2.z; s2.w += b2.w;
        }
        atomicAdd(&g_sum[cq * 4 + 0], s.x);  atomicAdd(&g_sum[cq * 4 + 1], s.y);
        atomicAdd(&g_sum[cq * 4 + 2], s.z);  atomicAdd(&g_sum[cq * 4 + 3], s.w);
        atomicAdd(&g_sumsq[cq * 4 + 0], s2.x); atomicAdd(&g_sumsq[cq * 4 + 1], s2.y);
        atomicAdd(&g_sumsq[cq * 4 + 2], s2.z); atomicAdd(&g_sumsq[cq * 4 + 3], s2.w);
    }
}

// ---------------- L5: gather + affine + relu + max (float4) ----------------
__global__ __launch_bounds__(256) void out_kernel(const float* __restrict__ gamma,
                                                  const float* __restrict__ beta,
                                                  float* __restrict__ out) {
    __shared__ int gi[NS_];
    __shared__ float4 rmx[64][4];
    __shared__ float4 rmn[64][4];
    const int q = blockIdx.x;
    const int tid = threadIdx.x;
    if (tid < NS_) gi[tid] = g_gidx[q * NS_ + tid];
    __syncthreads();

    const int cq = tid & 63;
    const int p  = tid >> 6;
    const int b  = q >> 10;
    const float* F = g_feats2 + (size_t)b * N_ * COUT + cq * 4;

    float4 mx = make_float4(-3.4e38f, -3.4e38f, -3.4e38f, -3.4e38f);
    float4 mn = make_float4( 3.4e38f,  3.4e38f,  3.4e38f,  3.4e38f);
#pragma unroll
    for (int j = 0; j < 8; j++) {
        float4 v = *(const float4*)(F + (size_t)gi[p * 8 + j] * COUT);
        mx.x = fmaxf(mx.x, v.x); mx.y = fmaxf(mx.y, v.y);
        mx.z = fmaxf(mx.z, v.z); mx.w = fmaxf(mx.w, v.w);
        mn.x = fminf(mn.x, v.x); mn.y = fminf(mn.y, v.y);
        mn.z = fminf(mn.z, v.z); mn.w = fminf(mn.w, v.w);
    }
    rmx[cq][p] = mx;
    rmn[cq][p] = mn;
    __syncthreads();

    if (p == 0) {
#pragma unroll
        for (int j = 1; j < 4; j++) {
            float4 a = rmx[cq][j], c = rmn[cq][j];
            mx.x = fmaxf(mx.x, a.x); mx.y = fmaxf(mx.y, a.y);
            mx.z = fmaxf(mx.z, a.z); mx.w = fmaxf(mx.w, a.w);
            mn.x = fminf(mn.x, c.x); mn.y = fminf(mn.y, c.y);
            mn.z = fminf(mn.z, c.z); mn.w = fminf(mn.w, c.w);
        }
        const float M = (float)(B_ * S_ * NS_);
        float4 sm  = *(const float4*)(g_sum   + cq * 4);
        float4 sq  = *(const float4*)(g_sumsq + cq * 4);
        float4 ga  = *(const float4*)(gamma + cq * 4);
        float4 be  = *(const float4*)(beta  + cq * 4);
        float4 o;
        {
            float mean = sm.x / M, var = sq.x / M - mean * mean;
            float sc = ga.x * rsqrtf(var + 1e-5f);
            float mm = (sc >= 0.f) ? mx.x : mn.x;
            o.x = fmaxf(fmaf(sc, mm, be.x - mean * sc), 0.f);
        }
        {
            float mean = sm.y / M, var = sq.y / M - mean * mean;
            float sc = ga.y * rsqrtf(var + 1e-5f);
            float mm = (sc >= 0.f) ? mx.y : mn.y;
            o.y = fmaxf(fmaf(sc, mm, be.y - mean * sc), 0.f);
        }
        {
            float mean = sm.z / M, var = sq.z / M - mean * mean;
            float sc = ga.z * rsqrtf(var + 1e-5f);
            float mm = (sc >= 0.f) ? mx.z : mn.z;
            o.z = fmaxf(fmaf(sc, mm, be.z - mean * sc), 0.f);
        }
        {
            float mean = sm.w / M, var = sq.w / M - mean * mean;
            float sc = ga.w * rsqrtf(var + 1e-5f);
            float mm = (sc >= 0.f) ? mx.w : mn.w;
            o.w = fmaxf(fmaf(sc, mm, be.w - mean * sc), 0.f);
        }
        *(float4*)(out + (size_t)q * COUT + cq * 4) = o;
    }
}

// ---------------- launch ----------------
extern "C" void kernel_launch(void* const* d_in, const int* in_sizes, int n_in,
                              void* d_out, int out_size) {
    const float* xyz    = (const float*)d_in[0];
    const float* points = (const float*)d_in[2];
    const float* W1     = (const float*)d_in[3];
    const float* b1     = (const float*)d_in[4];
    const float* Wc     = (const float*)d_in[5];
    const float* bc     = (const float*)d_in[6];
    const float* gamma  = (const float*)d_in[7];
    const float* beta   = (const float*)d_in[8];
    float* out = (float*)d_out;

    prep_kernel<<<113, 256>>>(xyz, W1, b1, Wc, bc);
    fps_gemm_kernel<<<8 + 1024, 512>>>(xyz, points);
    ball_kernel<<<1024, 256>>>();
    stats_kernel<<<1024, 256>>>();
    out_kernel<<<8192, 256>>>(gamma, beta, out);
}

// round 11
// speedup vs baseline: 1.0752x; 1.0752x over previous
#include <cuda_runtime.h>
#include <cstdint>

#define B_   8
#define N_   4096
#define S_   1024
#define NS_  32
#define CIN  64
#define CMLP 128
#define COUT 256
#define R2_  0.0225f   // 0.15^2

// ---------------- scratch ----------------
__device__ float  g_W[CIN * COUT];
__device__ float  g_bias2[COUT];
__device__ float  g_feats2[(size_t)B_ * N_ * COUT];
__device__ int    g_fps[B_ * S_];
__device__ int    g_gidx[B_ * S_ * NS_];
__device__ int    g_cnt[B_ * N_];
__device__ float  g_sum[COUT];
__device__ float  g_sumsq[COUT];
__device__ float4 g_xyz4[B_ * N_];     // xyz staged as float4 (orig order)
__device__ float4 g_pts4[B_ * N_];     // cell-permuted points (x,y,z,orig-id)

// ---------------- L1: prep ----------------
__global__ __launch_bounds__(256) void prep_kernel(const float* __restrict__ xyz,
                                                   const float* __restrict__ W1,
                                                   const float* __restrict__ b1,
                                                   const float* __restrict__ Wc,
                                                   const float* __restrict__ bc) {
    int bx = blockIdx.x, tid = threadIdx.x;
    if (bx < 64) {
        float acc = 0.f;
        const float* w1 = W1 + bx * CMLP;
#pragma unroll 8
        for (int m = 0; m < CMLP; m++) acc = fmaf(w1[m], Wc[m * COUT + tid], acc);
        g_W[bx * COUT + tid] = acc;
    } else if (bx == 64) {
        float acc = bc[tid];
#pragma unroll 8
        for (int m = 0; m < CMLP; m++) acc = fmaf(b1[m], Wc[m * COUT + tid], acc);
        g_bias2[tid] = acc;
        g_sum[tid] = 0.f;
        g_sumsq[tid] = 0.f;
    } else if (bx < 81) {
        int base = (bx - 65) * 2048 + tid;
#pragma unroll
        for (int i = 0; i < 8; i++) g_cnt[base + i * 256] = 0;
    } else {
        int base = (bx - 81) * 1024 + tid;
#pragma unroll
        for (int i = 0; i < 4; i++) {
            int p = base + i * 256;
            g_xyz4[p] = make_float4(xyz[p * 3 + 0], xyz[p * 3 + 1], xyz[p * 3 + 2], 0.f);
        }
    }
}

// ---------------- L2: fused FPS (blocks 0..7, 512 thr) + feats2 GEMM ----------------
__global__ __launch_bounds__(512) void fps_gemm_kernel(const float* __restrict__ xyz,
                                                       const float* __restrict__ points) {
    __shared__ __align__(16) char smem_raw[64 * 68 * 4];   // 17.4 KB union
    const int tid = threadIdx.x;
    const int lane = tid & 31, w = tid >> 5;

    if (blockIdx.x < B_) {
        // ============ FPS: one CTA (512 thr), 16^3 Morton sort, warp pruning ============
        const int b = blockIdx.x;
        const float* X = xyz + (size_t)b * N_ * 3;
        const int base = tid * 8;                       // 8 pts/thread
        const size_t bN = (size_t)b * N_;

        unsigned* cells = (unsigned*)smem_raw;                   // [4096] 16 KB
        unsigned* wsum  = (unsigned*)(smem_raw + 16384);         // [16]
        uint2*    swp   = (uint2*)(smem_raw + 16384 + 64);       // [2][16]

        // ---- prologue: counting-sort into 16x16x16 Morton cells ----
#pragma unroll
        for (int i = 0; i < 8; i++) cells[tid + i * 512] = 0;
        __syncthreads();

        float lx[8], ly[8], lz[8];
        int cid[8];
#pragma unroll
        for (int i = 0; i < 8; i++) {
            int p = base + i;
            lx[i] = X[p * 3 + 0]; ly[i] = X[p * 3 + 1]; lz[i] = X[p * 3 + 2];
            int ix = min(15, (int)(lx[i] * 16.f));
            int iy = min(15, (int)(ly[i] * 16.f));
            int iz = min(15, (int)(lz[i] * 16.f));
            int m = (ix & 1) | ((iy & 1) << 1) | ((iz & 1) << 2)
                  | ((ix & 2) << 2) | ((iy & 2) << 3) | ((iz & 2) << 4)
                  | ((ix & 4) << 4) | ((iy & 4) << 5) | ((iz & 4) << 6)
                  | ((ix & 8) << 6) | ((iy & 8) << 7) | ((iz & 8) << 8);
            cid[i] = m;
            atomicAdd(&cells[m], 1u);
        }
        __syncthreads();

        // exclusive scan over 4096 cells (8 consecutive per thread)
        {
            unsigned c8[8], tsum = 0;
#pragma unroll
            for (int i = 0; i < 8; i++) { c8[i] = cells[tid * 8 + i]; tsum += c8[i]; }
            unsigned inc = tsum;
#pragma unroll
            for (int o = 1; o < 32; o <<= 1) {
                unsigned n = __shfl_up_sync(0xffffffffu, inc, o);
                if (lane >= o) inc += n;
            }
            if (lane == 31) wsum[w] = inc;
            __syncthreads();
            if (tid < 16) {
                unsigned t = wsum[tid], s = t;
#pragma unroll
                for (int o = 1; o < 16; o <<= 1) {
                    unsigned n = __shfl_up_sync(0xffffu, s, o);
                    if (tid >= o) s += n;
                }
                wsum[tid] = s - t;
            }
            __syncthreads();
            unsigned run = wsum[w] + inc - tsum;
#pragma unroll
            for (int i = 0; i < 8; i++) { cells[tid * 8 + i] = run; run += c8[i]; }
            __syncthreads();
        }

        // scatter with original ids
#pragma unroll
        for (int i = 0; i < 8; i++) {
            unsigned pos = atomicAdd(&cells[cid[i]], 1u);
            g_pts4[bN + pos] = make_float4(lx[i], ly[i], lz[i], __int_as_float(base + i));
        }
        __syncthreads();

        // reload own 8 permuted points; warp bbox
        float px[8], py[8], pz[8], dm[8];
        int   pid[8];
        float tlx = 1e30f, tly = 1e30f, tlz = 1e30f;
        float thx = -1e30f, thy = -1e30f, thz = -1e30f;
#pragma unroll
        for (int i = 0; i < 8; i++) {
            float4 v = g_pts4[bN + base + i];
            px[i] = v.x; py[i] = v.y; pz[i] = v.z;
            pid[i] = __float_as_int(v.w);
            dm[i] = 1e10f;
            tlx = fminf(tlx, v.x); thx = fmaxf(thx, v.x);
            tly = fminf(tly, v.y); thy = fmaxf(thy, v.y);
            tlz = fminf(tlz, v.z); thz = fmaxf(thz, v.z);
        }
        const float wlx = __uint_as_float(__reduce_min_sync(0xffffffffu, __float_as_uint(tlx)));
        const float wly = __uint_as_float(__reduce_min_sync(0xffffffffu, __float_as_uint(tly)));
        const float wlz = __uint_as_float(__reduce_min_sync(0xffffffffu, __float_as_uint(tlz)));
        const float whx = __uint_as_float(__reduce_max_sync(0xffffffffu, __float_as_uint(thx)));
        const float why = __uint_as_float(__reduce_max_sync(0xffffffffu, __float_as_uint(thy)));
        const float whz = __uint_as_float(__reduce_max_sync(0xffffffffu, __float_as_uint(thz)));

        if (tid == 0) g_fps[b * S_ + 0] = 0;
        float4 c4 = __ldg(&g_xyz4[bN + 0]);
        float cx = c4.x, cy = c4.y, cz = c4.z;
        unsigned tmaxu  = __float_as_uint(1e10f);   // per-lane max(dm)
        unsigned wTmaxu = __float_as_uint(1e10f);   // cached warp max (uniform)
        unsigned wWinu  = 0u;                        // cached warp winner (~pid)

        for (int it = 1; it < S_; ++it) {
            // conservative lower bound centroid -> warp bbox
            float tx = fmaxf(fmaxf(wlx - cx, cx - whx), 0.f);
            float ty = fmaxf(fmaxf(wly - cy, cy - why), 0.f);
            float tz = fmaxf(fmaxf(wlz - cz, cz - whz), 0.f);
            float wLB = tx * tx;
            wLB = fmaf(ty, ty, wLB);
            wLB = fmaf(tz, tz, wLB);

            if (wLB * 0.999999f < __uint_as_float(wTmaxu)) {   // whole-warp scan
                float bestv = -1.f;
#pragma unroll
                for (int i = 0; i < 8; i++) {
                    float dx = px[i] - cx, dy = py[i] - cy, dz = pz[i] - cz;
                    float d = fmaf(dz, dz, fmaf(dy, dy, dx * dx));
                    float v = fminf(dm[i], d);
                    dm[i] = v;
                    bestv = fmaxf(bestv, v);
                }
                unsigned ub = __float_as_uint(bestv);
                unsigned m1 = __reduce_max_sync(0xffffffffu, ub);
                unsigned cand = 0u;
                if (ub == m1) {
                    float fM = __uint_as_float(m1);
                    int mid = 0x7fffffff;
#pragma unroll
                    for (int i = 0; i < 8; i++)
                        if (dm[i] == fM) mid = min(mid, pid[i]);
                    cand = ~(unsigned)mid;
                }
                wWinu = __reduce_max_sync(0xffffffffu, cand);
                tmaxu = ub;
                wTmaxu = m1;
            }
            // else: exact skip — cached (wTmaxu, wWinu, tmaxu) remain valid

            const int pr = it & 1;
            if (lane == 0) swp[pr * 16 + w] = make_uint2(wTmaxu, wWinu);
            __syncthreads();                                   // the ONLY barrier

            uint2 pv = swp[pr * 16 + (lane & 15)];
            unsigned M2 = __reduce_max_sync(0xffffffffu, pv.x);
            unsigned c2 = (pv.x == M2) ? pv.y : 0u;
            unsigned I2 = __reduce_max_sync(0xffffffffu, c2);
            int far = (int)(~I2);

            if (tid == 0) g_fps[b * S_ + it] = far;
            float4 cc = __ldg(&g_xyz4[bN + far]);
            cx = cc.x; cy = cc.y; cz = cc.z;
        }
    } else {
        // ============ GEMM (512 thr): feats2 = points @ W + bias2 ============
        float (*As)[68] = (float (*)[68])smem_raw;
        const int gb = blockIdx.x - B_;
        const int rt = gb & 511;
        const int ct = gb >> 9;

#pragma unroll
        for (int i = 0; i < 2; i++) {
            int f = tid + i * 512;
            int r = f >> 4, k4 = f & 15;
            float4 v = *(const float4*)(points + ((size_t)(rt * 64 + r)) * 64 + k4 * 4);
            As[k4 * 4 + 0][r] = v.x;
            As[k4 * 4 + 1][r] = v.y;
            As[k4 * 4 + 2][r] = v.z;
            As[k4 * 4 + 3][r] = v.w;
        }
        __syncthreads();

        const int col0 = ct * 128 + (tid & 31) * 4;
        const int r0   = (tid >> 5) * 4;

        float acc[4][4];
#pragma unroll
        for (int i = 0; i < 4; i++)
#pragma unroll
            for (int j = 0; j < 4; j++) acc[i][j] = 0.f;

#pragma unroll 8
        for (int k = 0; k < 64; k++) {
            float4 b4 = *(const float4*)(g_W + k * COUT + col0);
            float4 a4 = *(const float4*)&As[k][r0];
            float a[4] = {a4.x, a4.y, a4.z, a4.w};
            float bv[4] = {b4.x, b4.y, b4.z, b4.w};
#pragma unroll
            for (int i = 0; i < 4; i++)
#pragma unroll
                for (int j = 0; j < 4; j++)
                    acc[i][j] = fmaf(a[i], bv[j], acc[i][j]);
        }

        float4 bb = *(const float4*)(g_bias2 + col0);
#pragma unroll
        for (int i = 0; i < 4; i++) {
            float4 o;
            o.x = acc[i][0] + bb.x;
            o.y = acc[i][1] + bb.y;
            o.z = acc[i][2] + bb.z;
            o.w = acc[i][3] + bb.w;
            *(float4*)(g_feats2 + ((size_t)(rt * 64 + r0 + i)) * COUT + col0) = o;
        }
    }
}

// ---------------- L3: ball query (one warp per query, float4 xyz) ----------------
__global__ __launch_bounds__(256) void ball_kernel() {
    const int w = threadIdx.x >> 5, lane = threadIdx.x & 31;
    const int q = blockIdx.x * 8 + w;
    const int b = q >> 10;
    const float4* X4 = g_xyz4 + (size_t)b * N_;
    const int ci = g_fps[q];
    float4 c = __ldg(&X4[ci]);

    int cnt = 0, first = -1;
    int* out = g_gidx + q * NS_;

    for (int base = 0; base < N_; base += 32) {
        int p = base + lane;
        float4 v = __ldg(&X4[p]);
        float dx = v.x - c.x, dy = v.y - c.y, dz = v.z - c.z;
        float d = fmaf(dz, dz, fmaf(dy, dy, dx * dx));
        bool in = (d <= R2_);
        unsigned bal = __ballot_sync(0xffffffffu, in);
        if (first < 0 && bal) first = base + __ffs(bal) - 1;
        int slot = cnt + __popc(bal & ((1u << lane) - 1));
        if (in && slot < NS_) {
            out[slot] = p;
            atomicAdd(&g_cnt[b * N_ + p], 1);
        }
        cnt += __popc(bal);
        if (cnt >= NS_) break;
    }
    if (cnt < NS_) {
        for (int s2 = cnt + lane; s2 < NS_; s2 += 32) out[s2] = first;
        if (lane == 0) atomicAdd(&g_cnt[b * N_ + first], NS_ - cnt);
    }
}

// ---------------- L4: count-weighted BN stats (128 blocks x 256 rows) ----------------
__global__ __launch_bounds__(256) void stats_kernel() {
    __shared__ float cf[256];
    __shared__ float4 red[64][4][2];
    const int tid = threadIdx.x;
    const int row0 = blockIdx.x * 256;
    cf[tid] = (float)g_cnt[row0 + tid];
    __syncthreads();

    const int cq = tid & 63;         // channel quad 0..63
    const int sr = tid >> 6;         // subrow group 0..3 (64 rows each)
    float4 s  = make_float4(0.f, 0.f, 0.f, 0.f);
    float4 s2 = make_float4(0.f, 0.f, 0.f, 0.f);
#pragma unroll 8
    for (int k = 0; k < 64; k++) {
        int r = sr * 64 + k;
        float c = cf[r];
        float4 v = *(const float4*)(g_feats2 + (size_t)(row0 + r) * COUT + cq * 4);
        float ax = c * v.x, ay = c * v.y, az = c * v.z, aw = c * v.w;
        s.x += ax; s.y += ay; s.z += az; s.w += aw;
        s2.x = fmaf(ax, v.x, s2.x);
        s2.y = fmaf(ay, v.y, s2.y);
        s2.z = fmaf(az, v.z, s2.z);
        s2.w = fmaf(aw, v.w, s2.w);
    }
    red[cq][sr][0] = s;
    red[cq][sr][1] = s2;
    __syncthreads();

    if (sr == 0) {
#pragma unroll
        for (int j = 1; j < 4; j++) {
            float4 a = red[cq][j][0], b2 = red[cq][j][1];
            s.x += a.x; s.y += a.y; s.z += a.z; s.w += a.w;
            s2.x += b2.x; s2.y += b2.y; s2.z += b2.z; s2.w += b2.w;
        }
        atomicAdd(&g_sum[cq * 4 + 0], s.x);  atomicAdd(&g_sum[cq * 4 + 1], s.y);
        atomicAdd(&g_sum[cq * 4 + 2], s.z);  atomicAdd(&g_sum[cq * 4 + 3], s.w);
        atomicAdd(&g_sumsq[cq * 4 + 0], s2.x); atomicAdd(&g_sumsq[cq * 4 + 1], s2.y);
        atomicAdd(&g_sumsq[cq * 4 + 2], s2.z); atomicAdd(&g_sumsq[cq * 4 + 3], s2.w);
    }
}

// ---------------- L5: gather + affine + relu + max (float4) ----------------
__global__ __launch_bounds__(256) void out_kernel(const float* __restrict__ gamma,
                                                  const float* __restrict__ beta,
                                                  float* __restrict__ out) {
    __shared__ int gi[NS_];
    __shared__ float4 rmx[64][4];
    __shared__ float4 rmn[64][4];
    const int q = blockIdx.x;
    const int tid = threadIdx.x;
    if (tid < NS_) gi[tid] = g_gidx[q * NS_ + tid];
    __syncthreads();

    const int cq = tid & 63;
    const int p  = tid >> 6;
    const int b  = q >> 10;
    const float* F = g_feats2 + (size_t)b * N_ * COUT + cq * 4;

    float4 mx = make_float4(-3.4e38f, -3.4e38f, -3.4e38f, -3.4e38f);
    float4 mn = make_float4( 3.4e38f,  3.4e38f,  3.4e38f,  3.4e38f);
#pragma unroll
    for (int j = 0; j < 8; j++) {
        float4 v = *(const float4*)(F + (size_t)gi[p * 8 + j] * COUT);
        mx.x = fmaxf(mx.x, v.x); mx.y = fmaxf(mx.y, v.y);
        mx.z = fmaxf(mx.z, v.z); mx.w = fmaxf(mx.w, v.w);
        mn.x = fminf(mn.x, v.x); mn.y = fminf(mn.y, v.y);
        mn.z = fminf(mn.z, v.z); mn.w = fminf(mn.w, v.w);
    }
    rmx[cq][p] = mx;
    rmn[cq][p] = mn;
    __syncthreads();

    if (p == 0) {
#pragma unroll
        for (int j = 1; j < 4; j++) {
            float4 a = rmx[cq][j], c = rmn[cq][j];
            mx.x = fmaxf(mx.x, a.x); mx.y = fmaxf(mx.y, a.y);
            mx.z = fmaxf(mx.z, a.z); mx.w = fmaxf(mx.w, a.w);
            mn.x = fminf(mn.x, c.x); mn.y = fminf(mn.y, c.y);
            mn.z = fminf(mn.z, c.z); mn.w = fminf(mn.w, c.w);
        }
        const float M = (float)(B_ * S_ * NS_);
        float4 sm  = *(const float4*)(g_sum   + cq * 4);
        float4 sq  = *(const float4*)(g_sumsq + cq * 4);
        float4 ga  = *(const float4*)(gamma + cq * 4);
        float4 be  = *(const float4*)(beta  + cq * 4);
        float4 o;
        {
            float mean = sm.x / M, var = sq.x / M - mean * mean;
            float sc = ga.x * rsqrtf(var + 1e-5f);
            float mm = (sc >= 0.f) ? mx.x : mn.x;
            o.x = fmaxf(fmaf(sc, mm, be.x - mean * sc), 0.f);
        }
        {
            float mean = sm.y / M, var = sq.y / M - mean * mean;
            float sc = ga.y * rsqrtf(var + 1e-5f);
            float mm = (sc >= 0.f) ? mx.y : mn.y;
            o.y = fmaxf(fmaf(sc, mm, be.y - mean * sc), 0.f);
        }
        {
            float mean = sm.z / M, var = sq.z / M - mean * mean;
            float sc = ga.z * rsqrtf(var + 1e-5f);
            float mm = (sc >= 0.f) ? mx.z : mn.z;
            o.z = fmaxf(fmaf(sc, mm, be.z - mean * sc), 0.f);
        }
        {
            float mean = sm.w / M, var = sq.w / M - mean * mean;
            float sc = ga.w * rsqrtf(var + 1e-5f);
            float mm = (sc >= 0.f) ? mx.w : mn.w;
            o.w = fmaxf(fmaf(sc, mm, be.w - mean * sc), 0.f);
        }
        *(float4*)(out + (size_t)q * COUT + cq * 4) = o;
    }
}

// ---------------- launch ----------------
extern "C" void kernel_launch(void* const* d_in, const int* in_sizes, int n_in,
                              void* d_out, int out_size) {
    const float* xyz    = (const float*)d_in[0];
    const float* points = (const float*)d_in[2];
    const float* W1     = (const float*)d_in[3];
    const float* b1     = (const float*)d_in[4];
    const float* Wc     = (const float*)d_in[5];
    const float* bc     = (const float*)d_in[6];
    const float* gamma  = (const float*)d_in[7];
    const float* beta   = (const float*)d_in[8];
    float* out = (float*)d_out;

    prep_kernel<<<113, 256>>>(xyz, W1, b1, Wc, bc);
    fps_gemm_kernel<<<8 + 1024, 512>>>(xyz, points);
    ball_kernel<<<1024, 256>>>();
    stats_kernel<<<128, 256>>>();
    out_kernel<<<8192, 256>>>(gamma, beta, out);
}

// round 12
// speedup vs baseline: 1.1013x; 1.0244x over previous
#include <cuda_runtime.h>
#include <cstdint>

#define B_   8
#define N_   4096
#define S_   1024
#define NS_  32
#define CIN  64
#define CMLP 128
#define COUT 256
#define R2_  0.0225f   // 0.15^2

// ---------------- scratch ----------------
__device__ float  g_W[CIN * COUT];
__device__ float  g_bias2[COUT];
__device__ float  g_feats2[(size_t)B_ * N_ * COUT];
__device__ int    g_fps[B_ * S_];
__device__ int    g_gidx[B_ * S_ * NS_];
__device__ int    g_cnt[B_ * N_];
__device__ float  g_sum[COUT];
__device__ float  g_sumsq[COUT];
__device__ float4 g_xyz4[B_ * N_];     // xyz staged as float4 (orig order)
__device__ float4 g_pts4[B_ * N_];     // cell-permuted points (x,y,z,orig-id)

// ---------------- L1: prep ----------------
__global__ __launch_bounds__(256) void prep_kernel(const float* __restrict__ xyz,
                                                   const float* __restrict__ W1,
                                                   const float* __restrict__ b1,
                                                   const float* __restrict__ Wc,
                                                   const float* __restrict__ bc) {
    int bx = blockIdx.x, tid = threadIdx.x;
    if (bx < 64) {
        float acc = 0.f;
        const float* w1 = W1 + bx * CMLP;
#pragma unroll 8
        for (int m = 0; m < CMLP; m++) acc = fmaf(w1[m], Wc[m * COUT + tid], acc);
        g_W[bx * COUT + tid] = acc;
    } else if (bx == 64) {
        float acc = bc[tid];
#pragma unroll 8
        for (int m = 0; m < CMLP; m++) acc = fmaf(b1[m], Wc[m * COUT + tid], acc);
        g_bias2[tid] = acc;
        g_sum[tid] = 0.f;
        g_sumsq[tid] = 0.f;
    } else if (bx < 81) {
        int base = (bx - 65) * 2048 + tid;
#pragma unroll
        for (int i = 0; i < 8; i++) g_cnt[base + i * 256] = 0;
    } else {
        int base = (bx - 81) * 1024 + tid;
#pragma unroll
        for (int i = 0; i < 4; i++) {
            int p = base + i * 256;
            g_xyz4[p] = make_float4(xyz[p * 3 + 0], xyz[p * 3 + 1], xyz[p * 3 + 2], 0.f);
        }
    }
}

// ---------------- L2: fused FPS (blocks 0..7, 1024 thr) + feats2 GEMM ----------------
__global__ __launch_bounds__(1024, 1) void fps_gemm_kernel(const float* __restrict__ xyz,
                                                           const float* __restrict__ points) {
    __shared__ __align__(16) char smem_raw[64 * 68 * 4];   // 17.4 KB union
    const int tid = threadIdx.x;
    const int lane = tid & 31, w = tid >> 5;               // 32 warps

    if (blockIdx.x < B_) {
        // ============ FPS: one CTA (1024 thr), 16^3 Morton sort, warp pruning ============
        const int b = blockIdx.x;
        const float* X = xyz + (size_t)b * N_ * 3;
        const int base = tid * 4;                           // 4 pts/thread
        const size_t bN = (size_t)b * N_;

        unsigned* cells = (unsigned*)smem_raw;                   // [4096] 16 KB
        unsigned* wsum  = (unsigned*)(smem_raw + 16384);         // [32]
        uint2*    swp   = (uint2*)(smem_raw + 16384 + 128);      // [2][32]

        // ---- prologue: counting-sort into 16x16x16 Morton cells ----
#pragma unroll
        for (int i = 0; i < 4; i++) cells[tid + i * 1024] = 0;
        __syncthreads();

        float lx[4], ly[4], lz[4];
        int cid[4];
#pragma unroll
        for (int i = 0; i < 4; i++) {
            int p = base + i;
            lx[i] = X[p * 3 + 0]; ly[i] = X[p * 3 + 1]; lz[i] = X[p * 3 + 2];
            int ix = min(15, (int)(lx[i] * 16.f));
            int iy = min(15, (int)(ly[i] * 16.f));
            int iz = min(15, (int)(lz[i] * 16.f));
            int m = (ix & 1) | ((iy & 1) << 1) | ((iz & 1) << 2)
                  | ((ix & 2) << 2) | ((iy & 2) << 3) | ((iz & 2) << 4)
                  | ((ix & 4) << 4) | ((iy & 4) << 5) | ((iz & 4) << 6)
                  | ((ix & 8) << 6) | ((iy & 8) << 7) | ((iz & 8) << 8);
            cid[i] = m;
            atomicAdd(&cells[m], 1u);
        }
        __syncthreads();

        // exclusive scan over 4096 cells (4 consecutive per thread)
        {
            unsigned c4[4], tsum = 0;
#pragma unroll
            for (int i = 0; i < 4; i++) { c4[i] = cells[tid * 4 + i]; tsum += c4[i]; }
            unsigned inc = tsum;
#pragma unroll
            for (int o = 1; o < 32; o <<= 1) {
                unsigned n = __shfl_up_sync(0xffffffffu, inc, o);
                if (lane >= o) inc += n;
            }
            if (lane == 31) wsum[w] = inc;
            __syncthreads();
            if (tid < 32) {
                unsigned t = wsum[tid], s = t;
#pragma unroll
                for (int o = 1; o < 32; o <<= 1) {
                    unsigned n = __shfl_up_sync(0xffffffffu, s, o);
                    if (tid >= o) s += n;
                }
                wsum[tid] = s - t;
            }
            __syncthreads();
            unsigned run = wsum[w] + inc - tsum;
#pragma unroll
            for (int i = 0; i < 4; i++) { cells[tid * 4 + i] = run; run += c4[i]; }
            __syncthreads();
        }

        // scatter with original ids
#pragma unroll
        for (int i = 0; i < 4; i++) {
            unsigned pos = atomicAdd(&cells[cid[i]], 1u);
            g_pts4[bN + pos] = make_float4(lx[i], ly[i], lz[i], __int_as_float(base + i));
        }
        __syncthreads();

        // reload own 4 permuted points; warp bbox (128 pts ~ 0.5x0.25x0.25 region)
        float px[4], py[4], pz[4], dm[4];
        int   pid[4];
        float tlx = 1e30f, tly = 1e30f, tlz = 1e30f;
        float thx = -1e30f, thy = -1e30f, thz = -1e30f;
#pragma unroll
        for (int i = 0; i < 4; i++) {
            float4 v = g_pts4[bN + base + i];
            px[i] = v.x; py[i] = v.y; pz[i] = v.z;
            pid[i] = __float_as_int(v.w);
            dm[i] = 1e10f;
            tlx = fminf(tlx, v.x); thx = fmaxf(thx, v.x);
            tly = fminf(tly, v.y); thy = fmaxf(thy, v.y);
            tlz = fminf(tlz, v.z); thz = fmaxf(thz, v.z);
        }
        const float wlx = __uint_as_float(__reduce_min_sync(0xffffffffu, __float_as_uint(tlx)));
        const float wly = __uint_as_float(__reduce_min_sync(0xffffffffu, __float_as_uint(tly)));
        const float wlz = __uint_as_float(__reduce_min_sync(0xffffffffu, __float_as_uint(tlz)));
        const float whx = __uint_as_float(__reduce_max_sync(0xffffffffu, __float_as_uint(thx)));
        const float why = __uint_as_float(__reduce_max_sync(0xffffffffu, __float_as_uint(thy)));
        const float whz = __uint_as_float(__reduce_max_sync(0xffffffffu, __float_as_uint(thz)));

        if (tid == 0) g_fps[b * S_ + 0] = 0;
        float4 c4v = __ldg(&g_xyz4[bN + 0]);
        float cx = c4v.x, cy = c4v.y, cz = c4v.z;
        unsigned tmaxu  = __float_as_uint(1e10f);   // per-lane max(dm)
        unsigned wTmaxu = __float_as_uint(1e10f);   // cached warp max (uniform)
        unsigned wWinu  = 0u;                        // cached warp winner (~pid)

        for (int it = 1; it < S_; ++it) {
            // conservative lower bound centroid -> warp bbox
            float tx = fmaxf(fmaxf(wlx - cx, cx - whx), 0.f);
            float ty = fmaxf(fmaxf(wly - cy, cy - why), 0.f);
            float tz = fmaxf(fmaxf(wlz - cz, cz - whz), 0.f);
            float wLB = tx * tx;
            wLB = fmaf(ty, ty, wLB);
            wLB = fmaf(tz, tz, wLB);

            if (wLB * 0.999999f < __uint_as_float(wTmaxu)) {   // whole-warp scan
                float bestv = -1.f;
#pragma unroll
                for (int i = 0; i < 4; i++) {
                    float dx = px[i] - cx, dy = py[i] - cy, dz = pz[i] - cz;
                    float d = fmaf(dz, dz, fmaf(dy, dy, dx * dx));
                    float v = fminf(dm[i], d);
                    dm[i] = v;
                    bestv = fmaxf(bestv, v);
                }
                unsigned ub = __float_as_uint(bestv);
                unsigned m1 = __reduce_max_sync(0xffffffffu, ub);
                unsigned cand = 0u;
                if (ub == m1) {
                    float fM = __uint_as_float(m1);
                    int mid = 0x7fffffff;
#pragma unroll
                    for (int i = 0; i < 4; i++)
                        if (dm[i] == fM) mid = min(mid, pid[i]);
                    cand = ~(unsigned)mid;
                }
                wWinu = __reduce_max_sync(0xffffffffu, cand);
                tmaxu = ub;
                wTmaxu = m1;
            }
            // else: exact skip — cached (wTmaxu, wWinu, tmaxu) remain valid

            const int pr = it & 1;
            if (lane == 0) swp[pr * 32 + w] = make_uint2(wTmaxu, wWinu);
            __syncthreads();                                   // the ONLY barrier

            uint2 pv = swp[pr * 32 + lane];
            unsigned M2 = __reduce_max_sync(0xffffffffu, pv.x);
            unsigned c2 = (pv.x == M2) ? pv.y : 0u;
            unsigned I2 = __reduce_max_sync(0xffffffffu, c2);
            int far = (int)(~I2);

            if (tid == 0) g_fps[b * S_ + it] = far;
            float4 cc = __ldg(&g_xyz4[bN + far]);
            cx = cc.x; cy = cc.y; cz = cc.z;
        }
    } else {
        // ============ GEMM (1024 thr): feats2 = points @ W + bias2 ============
        float (*As)[68] = (float (*)[68])smem_raw;
        const int gb = blockIdx.x - B_;
        const int rt = gb & 511;
        const int ct = gb >> 9;

        // cooperative A-tile load: 1024 float4, 1 per thread, store transposed
        {
            int r = tid >> 4, k4 = tid & 15;
            float4 v = *(const float4*)(points + ((size_t)(rt * 64 + r)) * 64 + k4 * 4);
            As[k4 * 4 + 0][r] = v.x;
            As[k4 * 4 + 1][r] = v.y;
            As[k4 * 4 + 2][r] = v.z;
            As[k4 * 4 + 3][r] = v.w;
        }
        __syncthreads();

        const int col0 = ct * 128 + (tid & 31) * 4;
        const int r0   = (tid >> 5) * 2;        // 32 row-groups x 2 rows

        float acc[2][4];
#pragma unroll
        for (int i = 0; i < 2; i++)
#pragma unroll
            for (int j = 0; j < 4; j++) acc[i][j] = 0.f;

#pragma unroll 8
        for (int k = 0; k < 64; k++) {
            float4 b4 = *(const float4*)(g_W + k * COUT + col0);
            float2 a2 = *(const float2*)&As[k][r0];
            float a[2] = {a2.x, a2.y};
            float bv[4] = {b4.x, b4.y, b4.z, b4.w};
#pragma unroll
            for (int i = 0; i < 2; i++)
#pragma unroll
                for (int j = 0; j < 4; j++)
                    acc[i][j] = fmaf(a[i], bv[j], acc[i][j]);
        }

        float4 bb = *(const float4*)(g_bias2 + col0);
#pragma unroll
        for (int i = 0; i < 2; i++) {
            float4 o;
            o.x = acc[i][0] + bb.x;
            o.y = acc[i][1] + bb.y;
            o.z = acc[i][2] + bb.z;
            o.w = acc[i][3] + bb.w;
            *(float4*)(g_feats2 + ((size_t)(rt * 64 + r0 + i)) * COUT + col0) = o;
        }
    }
}

// ---------------- L3: ball query (one warp per query, float4 xyz) ----------------
__global__ __launch_bounds__(256) void ball_kernel() {
    const int w = threadIdx.x >> 5, lane = threadIdx.x & 31;
    const int q = blockIdx.x * 8 + w;
    const int b = q >> 10;
    const float4* X4 = g_xyz4 + (size_t)b * N_;
    const int ci = g_fps[q];
    float4 c = __ldg(&X4[ci]);

    int cnt = 0, first = -1;
    int* out = g_gidx + q * NS_;

    for (int base = 0; base < N_; base += 32) {
        int p = base + lane;
        float4 v = __ldg(&X4[p]);
        float dx = v.x - c.x, dy = v.y - c.y, dz = v.z - c.z;
        float d = fmaf(dz, dz, fmaf(dy, dy, dx * dx));
        bool in = (d <= R2_);
        unsigned bal = __ballot_sync(0xffffffffu, in);
        if (first < 0 && bal) first = base + __ffs(bal) - 1;
        int slot = cnt + __popc(bal & ((1u << lane) - 1));
        if (in && slot < NS_) {
            out[slot] = p;
            atomicAdd(&g_cnt[b * N_ + p], 1);
        }
        cnt += __popc(bal);
        if (cnt >= NS_) break;
    }
    if (cnt < NS_) {
        for (int s2 = cnt + lane; s2 < NS_; s2 += 32) out[s2] = first;
        if (lane == 0) atomicAdd(&g_cnt[b * N_ + first], NS_ - cnt);
    }
}

// ---------------- L4: count-weighted BN stats (512 blocks: 128 row x 4 chan chunks) ----------------
__global__ __launch_bounds__(256) void stats_kernel() {
    __shared__ float cf[256];
    __shared__ float4 red[16][16][2];
    const int tid = threadIdx.x;
    const int rc = blockIdx.x >> 2;        // row chunk 0..127 (256 rows each)
    const int cc = blockIdx.x & 3;         // channel chunk 0..3 (64 ch each)
    const int row0 = rc * 256;
    const int ch0  = cc * 64;

    cf[tid] = (float)g_cnt[row0 + tid];
    __syncthreads();

    const int rs = tid >> 4;               // row slot 0..15
    const int ql = tid & 15;               // quad lane 0..15 (4 channels each)
    float4 s  = make_float4(0.f, 0.f, 0.f, 0.f);
    float4 s2 = make_float4(0.f, 0.f, 0.f, 0.f);
#pragma unroll
    for (int k = 0; k < 16; k++) {
        int r = rs + k * 16;
        float c = cf[r];
        float4 v = *(const float4*)(g_feats2 + (size_t)(row0 + r) * COUT + ch0 + ql * 4);
        float ax = c * v.x, ay = c * v.y, az = c * v.z, aw = c * v.w;
        s.x += ax; s.y += ay; s.z += az; s.w += aw;
        s2.x = fmaf(ax, v.x, s2.x);
        s2.y = fmaf(ay, v.y, s2.y);
        s2.z = fmaf(az, v.z, s2.z);
        s2.w = fmaf(aw, v.w, s2.w);
    }
    red[rs][ql][0] = s;
    red[rs][ql][1] = s2;
    __syncthreads();

    if (rs == 0) {
#pragma unroll
        for (int j = 1; j < 16; j++) {
            float4 a = red[j][ql][0], b2 = red[j][ql][1];
            s.x += a.x; s.y += a.y; s.z += a.z; s.w += a.w;
            s2.x += b2.x; s2.y += b2.y; s2.z += b2.z; s2.w += b2.w;
        }
        const int c4 = ch0 + ql * 4;
        atomicAdd(&g_sum[c4 + 0], s.x);  atomicAdd(&g_sum[c4 + 1], s.y);
        atomicAdd(&g_sum[c4 + 2], s.z);  atomicAdd(&g_sum[c4 + 3], s.w);
        atomicAdd(&g_sumsq[c4 + 0], s2.x); atomicAdd(&g_sumsq[c4 + 1], s2.y);
        atomicAdd(&g_sumsq[c4 + 2], s2.z); atomicAdd(&g_sumsq[c4 + 3], s2.w);
    }
}

// ---------------- L5: gather + affine + relu + max (float4) ----------------
__global__ __launch_bounds__(256) void out_kernel(const float* __restrict__ gamma,
                                                  const float* __restrict__ beta,
                                                  float* __restrict__ out) {
    __shared__ int gi[NS_];
    __shared__ float4 rmx[64][4];
    __shared__ float4 rmn[64][4];
    const int q = blockIdx.x;
    const int tid = threadIdx.x;
    if (tid < NS_) gi[tid] = g_gidx[q * NS_ + tid];
    __syncthreads();

    const int cq = tid & 63;
    const int p  = tid >> 6;
    const int b  = q >> 10;
    const float* F = g_feats2 + (size_t)b * N_ * COUT + cq * 4;

    float4 mx = make_float4(-3.4e38f, -3.4e38f, -3.4e38f, -3.4e38f);
    float4 mn = make_float4( 3.4e38f,  3.4e38f,  3.4e38f,  3.4e38f);
#pragma unroll
    for (int j = 0; j < 8; j++) {
        float4 v = *(const float4*)(F + (size_t)gi[p * 8 + j] * COUT);
        mx.x = fmaxf(mx.x, v.x); mx.y = fmaxf(mx.y, v.y);
        mx.z = fmaxf(mx.z, v.z); mx.w = fmaxf(mx.w, v.w);
        mn.x = fminf(mn.x, v.x); mn.y = fminf(mn.y, v.y);
        mn.z = fminf(mn.z, v.z); mn.w = fminf(mn.w, v.w);
    }
    rmx[cq][p] = mx;
    rmn[cq][p] = mn;
    __syncthreads();

    if (p == 0) {
#pragma unroll
        for (int j = 1; j < 4; j++) {
            float4 a = rmx[cq][j], c = rmn[cq][j];
            mx.x = fmaxf(mx.x, a.x); mx.y = fmaxf(mx.y, a.y);
            mx.z = fmaxf(mx.z, a.z); mx.w = fmaxf(mx.w, a.w);
            mn.x = fminf(mn.x, c.x); mn.y = fminf(mn.y, c.y);
            mn.z = fminf(mn.z, c.z); mn.w = fminf(mn.w, c.w);
        }
        const float M = (float)(B_ * S_ * NS_);
        float4 sm  = *(const float4*)(g_sum   + cq * 4);
        float4 sq  = *(const float4*)(g_sumsq + cq * 4);
        float4 ga  = *(const float4*)(gamma + cq * 4);
        float4 be  = *(const float4*)(beta  + cq * 4);
        float4 o;
        {
            float mean = sm.x / M, var = sq.x / M - mean * mean;
            float sc = ga.x * rsqrtf(var + 1e-5f);
            float mm = (sc >= 0.f) ? mx.x : mn.x;
            o.x = fmaxf(fmaf(sc, mm, be.x - mean * sc), 0.f);
        }
        {
            float mean = sm.y / M, var = sq.y / M - mean * mean;
            float sc = ga.y * rsqrtf(var + 1e-5f);
            float mm = (sc >= 0.f) ? mx.y : mn.y;
            o.y = fmaxf(fmaf(sc, mm, be.y - mean * sc), 0.f);
        }
        {
            float mean = sm.z / M, var = sq.z / M - mean * mean;
            float sc = ga.z * rsqrtf(var + 1e-5f);
            float mm = (sc >= 0.f) ? mx.z : mn.z;
            o.z = fmaxf(fmaf(sc, mm, be.z - mean * sc), 0.f);
        }
        {
            float mean = sm.w / M, var = sq.w / M - mean * mean;
            float sc = ga.w * rsqrtf(var + 1e-5f);
            float mm = (sc >= 0.f) ? mx.w : mn.w;
            o.w = fmaxf(fmaf(sc, mm, be.w - mean * sc), 0.f);
        }
        *(float4*)(out + (size_t)q * COUT + cq * 4) = o;
    }
}

// ---------------- launch ----------------
extern "C" void kernel_launch(void* const* d_in, const int* in_sizes, int n_in,
                              void* d_out, int out_size) {
    const float* xyz    = (const float*)d_in[0];
    const float* points = (const float*)d_in[2];
    const float* W1     = (const float*)d_in[3];
    const float* b1     = (const float*)d_in[4];
    const float* Wc     = (const float*)d_in[5];
    const float* bc     = (const float*)d_in[6];
    const float* gamma  = (const float*)d_in[7];
    const float* beta   = (const float*)d_in[8];
    float* out = (float*)d_out;

    prep_kernel<<<113, 256>>>(xyz, W1, b1, Wc, bc);
    fps_gemm_kernel<<<8 + 1024, 1024>>>(xyz, points);
    ball_kernel<<<1024, 256>>>();
    stats_kernel<<<512, 256>>>();
    out_kernel<<<8192, 256>>>(gamma, beta, out);
}